// round 2
// baseline (speedup 1.0000x reference)
#include <cuda_runtime.h>

// Batched Kalman filter + forecast.
// Shapes (fixed for this problem): B=16384, T_total=504, L=336, H=168.
// One thread per batch row; sequential scan over time.
// Memory strategy: time is processed in chunks of 8 steps; each of the 5 input
// streams is loaded with 2x LDG.128 per chunk (rows are 16B-aligned, T%8==0),
// outputs are buffered in registers and written with 2x STG.128 per chunk.

#define TTOT 504
#define LHIST 336
#define HFCST 168

__device__ __forceinline__ void load8(float dst[8], const float4* base_f4, int chunk_f4) {
    float4 u = __ldg(base_f4 + chunk_f4);
    float4 v = __ldg(base_f4 + chunk_f4 + 1);
    dst[0] = u.x; dst[1] = u.y; dst[2] = u.z; dst[3] = u.w;
    dst[4] = v.x; dst[5] = v.y; dst[6] = v.z; dst[7] = v.w;
}

__global__ __launch_bounds__(64)
void kf_kernel(const float* __restrict__ T_obs,
               const float* __restrict__ T_air,
               const float* __restrict__ wind,
               const float* __restrict__ par,
               const float* __restrict__ dtv,
               const float* __restrict__ k_raw_p,
               const float* __restrict__ log_q_p,
               const float* __restrict__ log_r_p,
               const float* __restrict__ log_p0_p,
               const float* __restrict__ log_qs_p,
               const float* __restrict__ tpl_p,
               const float* __restrict__ tpq_p,
               const float* __restrict__ twc_p,
               const float* __restrict__ ts_p,
               const float* __restrict__ tfc_p,
               float* __restrict__ out,
               int B)
{
    int b = blockIdx.x * 64 + threadIdx.x;
    if (b >= B) return;

    // scalar params (L2-cached broadcast loads, negligible)
    const float k   = log1pf(expf(__ldg(k_raw_p)));   // softplus
    const float q   = expf(__ldg(log_q_p));
    const float qs  = expf(__ldg(log_qs_p));
    const float R   = expf(__ldg(log_r_p));
    const float P0  = expf(__ldg(log_p0_p));
    const float tpl = __ldg(tpl_p);
    const float tpq = __ldg(tpq_p);
    const float twc = __ldg(twc_p);
    const float ts  = __ldg(ts_p);
    const float tfc = __ldg(tfc_p);
    const float qq  = qs * q;   // q_scale * q

    const size_t rowoff = (size_t)b * TTOT;
    const float4* yR  = (const float4*)(T_obs + rowoff);
    const float4* taR = (const float4*)(T_air + rowoff);
    const float4* wR  = (const float4*)(wind  + rowoff);
    const float4* pR  = (const float4*)(par   + rowoff);
    const float4* dR  = (const float4*)(dtv   + rowoff);

    float s = 0.0f, P = P0;
    float pTa = 0.0f, pw = 0.0f, pp = 0.0f;   // inputs at t-1

    // -------- Filter phase: t = 0 .. L-1 (step applied for t = 1..L-1) ------
    for (int c = 0; c < LHIST; c += 8) {
        int f4 = c >> 2;
        float ta8[8], w8[8], p8[8], d8[8], y8[8];
        load8(ta8, taR, f4);
        load8(w8,  wR,  f4);
        load8(p8,  pR,  f4);
        load8(d8,  dR,  f4);
        load8(y8,  yR,  f4);

        #pragma unroll
        for (int i = 0; i < 8; i++) {
            int t = c + i;                       // uniform across warp
            if (t == 0) {
                s = y8[i]; pTa = ta8[i]; pw = w8[i]; pp = p8[i];
                continue;
            }
            float dtt = fmaxf(d8[i], 1.0f);
            // predict with inputs at t-1
            float dT = s - pTa;
            float cl = tpl * pp + tpq * pp * pp + twc * pw + ts * dT + tfc * pw * dT;
            float Tp = s - k * dT * dtt + cl * dtt;
            Tp = fminf(fmaxf(Tp, -50.0f), 100.0f);
            float F = 1.0f - k * dtt + (ts + tfc * pw) * dtt;
            F = fminf(fmaxf(F, -2.0f), 2.0f);
            float Pp = F * F * P + qq * dtt;
            Pp = fminf(fmaxf(Pp, 1e-10f), 1e6f);
            // update with observation at t
            float S = Pp + R;
            float K = Pp / S;
            s = Tp + K * (y8[i] - Tp);
            float omk = 1.0f - K;
            P = omk * omk * Pp + K * K * R;
            // carry inputs for next step
            pTa = ta8[i]; pw = w8[i]; pp = p8[i];
        }
    }

    // -------- Forecast phase: t = L .. T-1, outputs at index t-L ------------
    float4* outT = (float4*)(out + (size_t)b * HFCST);
    float4* outV = (float4*)(out + (size_t)B * HFCST + (size_t)b * HFCST);

    for (int c = LHIST; c < TTOT; c += 8) {
        int f4 = c >> 2;
        float ta8[8], w8[8], p8[8], d8[8];
        load8(ta8, taR, f4);
        load8(w8,  wR,  f4);
        load8(p8,  pR,  f4);
        load8(d8,  dR,  f4);

        float oT[8], oV[8];
        #pragma unroll
        for (int i = 0; i < 8; i++) {
            float dtt = fmaxf(d8[i], 1.0f);
            float dT = s - pTa;
            float cl = tpl * pp + tpq * pp * pp + twc * pw + ts * dT + tfc * pw * dT;
            float Tp = s - k * dT * dtt + cl * dtt;
            Tp = fminf(fmaxf(Tp, -50.0f), 100.0f);
            float F = 1.0f - k * dtt + (ts + tfc * pw) * dtt;
            F = fminf(fmaxf(F, -2.0f), 2.0f);
            float Pp = F * F * P + qq * dtt;
            Pp = fminf(fmaxf(Pp, 1e-10f), 1e6f);
            s = Tp; P = Pp;
            oT[i] = Tp; oV[i] = Pp;
            pTa = ta8[i]; pw = w8[i]; pp = p8[i];
        }

        int of4 = (c - LHIST) >> 2;
        outT[of4]     = make_float4(oT[0], oT[1], oT[2], oT[3]);
        outT[of4 + 1] = make_float4(oT[4], oT[5], oT[6], oT[7]);
        outV[of4]     = make_float4(oV[0], oV[1], oV[2], oV[3]);
        outV[of4 + 1] = make_float4(oV[4], oV[5], oV[6], oV[7]);
    }
}

extern "C" void kernel_launch(void* const* d_in, const int* in_sizes, int n_in,
                              void* d_out, int out_size) {
    const float* T_obs = (const float*)d_in[0];
    const float* T_air = (const float*)d_in[1];
    const float* wind  = (const float*)d_in[2];
    const float* par   = (const float*)d_in[3];
    const float* dtv   = (const float*)d_in[4];
    // d_in[5] = L_hist (unused; L=336 hardcoded, validated by shapes)
    const float* k_raw = (const float*)d_in[6];
    const float* log_q = (const float*)d_in[7];
    const float* log_r = (const float*)d_in[8];
    const float* log_p0 = (const float*)d_in[9];
    const float* log_qs = (const float*)d_in[10];
    const float* tpl = (const float*)d_in[11];
    const float* tpq = (const float*)d_in[12];
    const float* twc = (const float*)d_in[13];
    const float* ts_ = (const float*)d_in[14];
    const float* tfc = (const float*)d_in[15];

    int B = in_sizes[0] / TTOT;
    int blocks = (B + 63) / 64;
    kf_kernel<<<blocks, 64>>>(T_obs, T_air, wind, par, dtv,
                              k_raw, log_q, log_r, log_p0, log_qs,
                              tpl, tpq, twc, ts_, tfc,
                              (float*)d_out, B);
}

// round 3
// speedup vs baseline: 1.8703x; 1.8703x over previous
#include <cuda_runtime.h>

// Batched Kalman filter + forecast, B=16384 rows, T=504 (336 filter + 168 forecast).
// One thread per row for the sequential scan; memory goes through smem tiles:
//   - cp.async.cg 16B cooperative loads (coalesced), double-buffered
//   - smem row stride = 28 floats (7x16B groups, odd) -> conflict-free LDS.128
//   - forecast outputs staged in smem, flushed with coalesced 16B stores
// Math: P_update = (1-K)^2*Pp + K^2*R == K*R exactly (K = Pp/S, 1-K = R/S).

#define TTOT   504
#define LHIST  336
#define HFCST  168
#define TILE   24
#define NTILES 21      // 504/24
#define FTILES 14      // 336/24
#define RPB    64      // rows per block == threads per block
#define SROW   28      // smem floats per row (24 data + 4 pad; 7 x 16B groups)
#define SARR   (RPB*SROW)          // 1792 floats per array per buffer
#define SIN_FLOATS  (2*5*SARR)     // 17920 (double-buffered 5 input arrays)
#define SOUT_FLOATS (2*SARR)       // 3584  (T and V staging)
#define SMEM_BYTES  ((SIN_FLOATS + SOUT_FLOATS)*4)   // 86016 B

#define EL(v,i) ((i)==0?(v).x:((i)==1?(v).y:((i)==2?(v).z:(v).w)))

__global__ __launch_bounds__(RPB)
void kf_kernel(const float* __restrict__ T_obs,
               const float* __restrict__ T_air,
               const float* __restrict__ wind,
               const float* __restrict__ par,
               const float* __restrict__ dtv,
               const float* __restrict__ k_raw_p,
               const float* __restrict__ log_q_p,
               const float* __restrict__ log_r_p,
               const float* __restrict__ log_p0_p,
               const float* __restrict__ log_qs_p,
               const float* __restrict__ tpl_p,
               const float* __restrict__ tpq_p,
               const float* __restrict__ twc_p,
               const float* __restrict__ ts_p,
               const float* __restrict__ tfc_p,
               float* __restrict__ out,
               int B)
{
    extern __shared__ float smem[];
    float* sin   = smem;                    // [2][5][SARR]
    float* soutT = smem + SIN_FLOATS;       // [SARR]
    float* soutV = soutT + SARR;            // [SARR]

    const int tid  = threadIdx.x;
    const int row0 = blockIdx.x * RPB;
    const int b    = row0 + tid;

    // scalar params
    const float k   = log1pf(expf(__ldg(k_raw_p)));
    const float qq  = expf(__ldg(log_qs_p)) * expf(__ldg(log_q_p));
    const float R   = expf(__ldg(log_r_p));
    const float P0  = expf(__ldg(log_p0_p));
    const float tpl = __ldg(tpl_p);
    const float tpq = __ldg(tpq_p);
    const float twc = __ldg(twc_p);
    const float ts  = __ldg(ts_p);
    const float tfc = __ldg(tfc_p);

    const float* arrs[5] = {T_obs, T_air, wind, par, dtv};

    // state init: s = y[0]; prev inputs get set at (tile0,g0,i0)
    float s = __ldg(T_obs + (size_t)b * TTOT);
    float P = P0;
    float pTa = 0.0f, pw = 0.0f, pp = 0.0f;

    // ---- cooperative tile loader: 16B cp.async, coalesced across rows ------
    auto issue_tile = [&](int tile, int buf) {
        #pragma unroll
        for (int a = 0; a < 5; a++) {
            const float* gb = arrs[a];
            #pragma unroll
            for (int it = 0; it < 6; it++) {
                int q = tid + it * RPB;          // 0..383
                int r = q / 6, j = q % 6;        // row, 16B chunk within row
                const float* g = gb + (size_t)(row0 + r) * TTOT + tile * TILE + j * 4;
                float* ds = sin + (buf * 5 + a) * SARR + r * SROW + j * 4;
                unsigned du = (unsigned)__cvta_generic_to_shared(ds);
                asm volatile("cp.async.cg.shared.global [%0], [%1], 16;\n" :: "r"(du), "l"(g));
            }
        }
        asm volatile("cp.async.commit_group;\n");
    };

    issue_tile(0, 0);

    for (int tile = 0; tile < NTILES; ++tile) {
        const int buf = tile & 1;
        asm volatile("cp.async.wait_group 0;\n" ::: "memory");
        __syncthreads();                       // tile data ready; prev buffer free
        if (tile + 1 < NTILES) issue_tile(tile + 1, buf ^ 1);

        const float* by  = sin + (buf * 5 + 0) * SARR + tid * SROW;
        const float* bta = by  + SARR;
        const float* bw  = bta + SARR;
        const float* bp  = bw  + SARR;
        const float* bd  = bp  + SARR;

        if (tile < FTILES) {
            // -------- filter phase --------
            #pragma unroll
            for (int g = 0; g < 6; g++) {
                float4 y4 = *(const float4*)(by  + g * 4);
                float4 t4 = *(const float4*)(bta + g * 4);
                float4 w4 = *(const float4*)(bw  + g * 4);
                float4 p4 = *(const float4*)(bp  + g * 4);
                float4 d4 = *(const float4*)(bd  + g * 4);
                #pragma unroll
                for (int i = 0; i < 4; i++) {
                    float yv = EL(y4,i), tav = EL(t4,i), wv = EL(w4,i),
                          pv = EL(p4,i), dv = EL(d4,i);
                    bool do_step = !(g == 0 && i == 0 && tile == 0);   // skip t==0
                    if (do_step) {
                        float dtt = fmaxf(dv, 1.0f);
                        float dT  = s - pTa;
                        float cl  = tpl * pp + tpq * pp * pp + twc * pw
                                  + ts * dT + tfc * pw * dT;
                        float Tp  = s + (cl - k * dT) * dtt;
                        Tp = fminf(fmaxf(Tp, -50.0f), 100.0f);
                        float F = 1.0f + ((ts + tfc * pw) - k) * dtt;
                        F = fminf(fmaxf(F, -2.0f), 2.0f);
                        float Pp = F * F * P + qq * dtt;
                        Pp = fminf(fmaxf(Pp, 1e-10f), 1e6f);
                        float S = Pp + R;
                        float K = __fdividef(Pp, S);
                        s = Tp + K * (yv - Tp);
                        P = K * R;                 // == (1-K)^2*Pp + K^2*R
                    }
                    pTa = tav; pw = wv; pp = pv;
                }
            }
        } else {
            // -------- forecast phase --------
            #pragma unroll
            for (int g = 0; g < 6; g++) {
                float4 t4 = *(const float4*)(bta + g * 4);
                float4 w4 = *(const float4*)(bw  + g * 4);
                float4 p4 = *(const float4*)(bp  + g * 4);
                float4 d4 = *(const float4*)(bd  + g * 4);
                float oT[4], oV[4];
                #pragma unroll
                for (int i = 0; i < 4; i++) {
                    float tav = EL(t4,i), wv = EL(w4,i), pv = EL(p4,i), dv = EL(d4,i);
                    float dtt = fmaxf(dv, 1.0f);
                    float dT  = s - pTa;
                    float cl  = tpl * pp + tpq * pp * pp + twc * pw
                              + ts * dT + tfc * pw * dT;
                    float Tp  = s + (cl - k * dT) * dtt;
                    Tp = fminf(fmaxf(Tp, -50.0f), 100.0f);
                    float F = 1.0f + ((ts + tfc * wv * 0.0f + tfc * pw) - k) * dtt;
                    // note: F uses wind at t-1 (pw), same as filter
                    F = fminf(fmaxf(F, -2.0f), 2.0f);
                    float Pp = F * F * P + qq * dtt;
                    Pp = fminf(fmaxf(Pp, 1e-10f), 1e6f);
                    s = Tp; P = Pp;
                    oT[i] = Tp; oV[i] = Pp;
                    pTa = tav; pw = wv; pp = pv;
                }
                *(float4*)(soutT + tid * SROW + g * 4) = make_float4(oT[0], oT[1], oT[2], oT[3]);
                *(float4*)(soutV + tid * SROW + g * 4) = make_float4(oV[0], oV[1], oV[2], oV[3]);
            }
            __syncthreads();                   // outputs staged
            const int h0 = (tile - FTILES) * TILE;
            #pragma unroll
            for (int it = 0; it < 6; it++) {
                int q = tid + it * RPB;
                int r = q / 6, j = q % 6;
                size_t o = (size_t)(row0 + r) * HFCST + h0 + j * 4;
                *(float4*)(out + o) = *(const float4*)(soutT + r * SROW + j * 4);
                *(float4*)(out + (size_t)B * HFCST + o) = *(const float4*)(soutV + r * SROW + j * 4);
            }
            // next iteration's top __syncthreads orders sout reuse
        }
    }
}

extern "C" void kernel_launch(void* const* d_in, const int* in_sizes, int n_in,
                              void* d_out, int out_size) {
    const float* T_obs = (const float*)d_in[0];
    const float* T_air = (const float*)d_in[1];
    const float* wind  = (const float*)d_in[2];
    const float* par   = (const float*)d_in[3];
    const float* dtv   = (const float*)d_in[4];
    // d_in[5] = L_hist (compile-time constant 336)
    const float* k_raw  = (const float*)d_in[6];
    const float* log_q  = (const float*)d_in[7];
    const float* log_r  = (const float*)d_in[8];
    const float* log_p0 = (const float*)d_in[9];
    const float* log_qs = (const float*)d_in[10];
    const float* tpl = (const float*)d_in[11];
    const float* tpq = (const float*)d_in[12];
    const float* twc = (const float*)d_in[13];
    const float* ts_ = (const float*)d_in[14];
    const float* tfc = (const float*)d_in[15];

    int B = in_sizes[0] / TTOT;
    cudaFuncSetAttribute(kf_kernel, cudaFuncAttributeMaxDynamicSharedMemorySize, SMEM_BYTES);
    int blocks = (B + RPB - 1) / RPB;
    kf_kernel<<<blocks, RPB, SMEM_BYTES>>>(T_obs, T_air, wind, par, dtv,
                                           k_raw, log_q, log_r, log_p0, log_qs,
                                           tpl, tpq, twc, ts_, tfc,
                                           (float*)d_out, B);
}